// round 9
// baseline (speedup 1.0000x reference)
#include <cuda_runtime.h>
#include <cstdint>

// ---------------- problem constants ----------------
#define BB   2
#define VV   4
#define FD   128
#define ED   128
#define NHN  7
#define NN6  196608
#define NN5  49152
#define NN4  12288
#define PFN  32768
#define PP5  8192
#define PP4  2048
#define OO5  4
#define OO4  16

#define THREADS 512
#define TILE_M  32
#define NTILES  (BB * VV * (PFN / TILE_M))   // 8192
#define GRID    152                          // 1 persistent CTA per SM

#define AP 132                               // pitched rows (ldmatrix conflict-free)

// ---- smem layout (float offsets) ----
#define OFF_W     0
#define W_FLOATS  (ED * AP)                  // 16896
#define OFF_A     (OFF_W + W_FLOATS)
#define A_STAGE   (TILE_M * AP)              // 4224
#define OFF_R5    (OFF_A + 2 * A_STAGE)
#define R5_STAGE  (56 * FD)                  // 7168
#define OFF_R4    (OFF_R5 + 2 * R5_STAGE)
#define R4_STAGE  (14 * FD)                  // 1792
#define OFF_WT    (OFF_R4 + 2 * R4_STAGE)
#define WT_STAGE  448
#define OFF_IOUT  (OFF_WT + 2 * WT_STAGE)
#define IOUT_FLOATS (TILE_M * AP)            // 4224
#define SMEM_FLOATS (OFF_IOUT + IOUT_FLOATS) // 48384
#define SMEM_TOTAL  (SMEM_FLOATS * 4)        // 193536 B

typedef unsigned long long u64;

// scratch (device globals allowed)
__device__ float g_w5[BB * PP5 * OO5 * NHN];
__device__ float g_w4[BB * PP4 * OO4 * NHN];
__device__ float g_Wt[ED * FD];      // W transposed (n-major), rna-tf32 rounded

// ---------------- PTX helpers (baseline sm_80+ only) ----------------
__device__ __forceinline__ uint32_t f2tf32(float f) {
    uint32_t r; asm("cvt.rna.tf32.f32 %0, %1;" : "=r"(r) : "f"(f)); return r;
}
__device__ __forceinline__ u64 pack2(float s) {
    u64 r; unsigned ui = __float_as_uint(s);
    asm("mov.b64 %0, {%1, %1};" : "=l"(r) : "r"(ui));
    return r;
}
__device__ __forceinline__ u64 fma2(u64 a, u64 b, u64 c) {
    u64 d; asm("fma.rn.f32x2 %0, %1, %2, %3;" : "=l"(d) : "l"(a), "l"(b), "l"(c)); return d;
}
__device__ __forceinline__ void mma_tf32(float* c, const uint32_t* a,
                                         uint32_t b0, uint32_t b1) {
    asm volatile(
        "mma.sync.aligned.m16n8k8.row.col.f32.tf32.tf32.f32 "
        "{%0,%1,%2,%3}, {%4,%5,%6,%7}, {%8,%9}, {%0,%1,%2,%3};"
        : "+f"(c[0]), "+f"(c[1]), "+f"(c[2]), "+f"(c[3])
        : "r"(a[0]), "r"(a[1]), "r"(a[2]), "r"(a[3]), "r"(b0), "r"(b1));
}
__device__ __forceinline__ void ldsm4(uint32_t* r, uint32_t addr) {
    asm volatile("ldmatrix.sync.aligned.m8n8.x4.shared.b16 {%0,%1,%2,%3}, [%4];"
                 : "=r"(r[0]), "=r"(r[1]), "=r"(r[2]), "=r"(r[3]) : "r"(addr));
}
__device__ __forceinline__ void cp16(uint32_t dst, const void* src) {
    asm volatile("cp.async.cg.shared.global [%0], [%1], 16;" :: "r"(dst), "l"(src) : "memory");
}
#define CP_COMMIT() asm volatile("cp.async.commit_group;" ::: "memory")
#define CP_WAIT1()  asm volatile("cp.async.wait_group 1;" ::: "memory")

// ---------------- pre-pass: interp weights + W transpose w/ rna tf32 ----------------
__global__ void weights_kernel(const float* __restrict__ rd5, const float* __restrict__ m5,
                               const float* __restrict__ rd4, const float* __restrict__ m4,
                               const float* __restrict__ Wm)
{
    const int T5 = BB * PP5 * OO5;            // 65536
    const int T4 = BB * PP4 * OO4;            // 65536
    int t = blockIdx.x * blockDim.x + threadIdx.x;
    if (t < T5) {
        int pcb = t / OO5;
        const float* rd = rd5 + (size_t)t * NHN;
        const float* mm = m5 + (size_t)pcb * NHN;
        float w[NHN]; float s = 0.f;
#pragma unroll
        for (int n = 0; n < NHN; n++) { w[n] = 1.f / (1e-20f + rd[n] + mm[n] * 1e10f); s += w[n]; }
        float inv = 1.f / s;
#pragma unroll
        for (int n = 0; n < NHN; n++) g_w5[(size_t)t * NHN + n] = w[n] * inv;
    } else if (t < T5 + T4) {
        int tt = t - T5;
        int pcb = tt / OO4;
        const float* rd = rd4 + (size_t)tt * NHN;
        const float* mm = m4 + (size_t)pcb * NHN;
        float w[NHN]; float s = 0.f;
#pragma unroll
        for (int n = 0; n < NHN; n++) { w[n] = 1.f / (1e-20f + rd[n] + mm[n] * 1e10f); s += w[n]; }
        float inv = 1.f / s;
#pragma unroll
        for (int n = 0; n < NHN; n++) g_w4[(size_t)tt * NHN + n] = w[n] * inv;
    } else if (t < T5 + T4 + FD * ED) {
        int i = t - (T5 + T4);
        int k = i >> 7, n = i & 127;
        ((uint32_t*)g_Wt)[n * FD + k] = f2tf32(Wm[i]);    // transpose to n-major
    }
}

// ---------------- per-tile async staging ----------------
__device__ __forceinline__ void issue_tile(
    int t, int s, uint32_t sm_u,
    const float* __restrict__ table6, const float* __restrict__ table5,
    const float* __restrict__ table4,
    const int* __restrict__ var_idx, const int* __restrict__ idx6,
    const int* __restrict__ nh5, const int* __restrict__ nh4,
    int tid, int lane, int w)
{
    const int bv = t >> 10, tl = t & 1023;
    const int b = bv >> 2;
    const int vi = var_idx[bv];
    const float* tb6 = table6 + (size_t)vi * ((size_t)NN6 * FD);
    const float* tb5 = table5 + (size_t)vi * ((size_t)NN5 * FD);
    const float* tb4 = table4 + (size_t)vi * ((size_t)NN4 * FD);

    // A rows: 32 rows, 2 per warp
    {
        const int* i6 = idx6 + b * PFN + tl * TILE_M;
        const uint32_t aB = sm_u + (uint32_t)(OFF_A + s * A_STAGE) * 4u;
#pragma unroll
        for (int j = 0; j < 2; j++) {
            int rl = w * 2 + j;
            cp16(aB + (uint32_t)(rl * AP + lane * 4) * 4u,
                 tb6 + (size_t)i6[rl] * FD + lane * 4);
        }
    }
    // R5: 56 rows (warps 0..13, 4 rows each) / R4: 14 rows (warps 14,15, 7 each)
    if (w < 14) {
        const int base5 = (b * PP5 + tl * 8) * NHN;
        const uint32_t rB = sm_u + (uint32_t)(OFF_R5 + s * R5_STAGE) * 4u;
#pragma unroll
        for (int j = 0; j < 4; j++) {
            int r = w * 4 + j;
            int row = nh5[base5 + r];
            cp16(rB + (uint32_t)(r * FD + lane * 4) * 4u,
                 tb5 + (size_t)row * FD + lane * 4);
        }
    } else {
        const int base4 = (b * PP4 + tl * 2) * NHN;
        const uint32_t rB = sm_u + (uint32_t)(OFF_R4 + s * R4_STAGE) * 4u;
#pragma unroll
        for (int j = 0; j < 7; j++) {
            int r = (w - 14) * 7 + j;
            int row = nh4[base4 + r];
            cp16(rB + (uint32_t)(r * FD + lane * 4) * 4u,
                 tb4 + (size_t)row * FD + lane * 4);
        }
    }
    // interp weights: 224 + 224 floats = 112 chunks
    if (tid < 112) {
        const float* src = (tid < 56)
            ? g_w5 + (size_t)(b * PP5 + tl * 8) * (OO5 * NHN) + tid * 4
            : g_w4 + (size_t)(b * PP4 + tl * 2) * (OO4 * NHN) + (tid - 56) * 4;
        cp16(sm_u + (uint32_t)(OFF_WT + s * WT_STAGE + tid * 4) * 4u, src);
    }
}

// ---------------- persistent pipelined kernel ----------------
__global__ __launch_bounds__(THREADS, 1)
void embed_kernel(const float* __restrict__ table6, const float* __restrict__ table5,
                  const float* __restrict__ table4,
                  const float* __restrict__ bias,
                  const int* __restrict__ var_idx, const int* __restrict__ idx6,
                  const int* __restrict__ nh5, const int* __restrict__ nh4,
                  float* __restrict__ out)
{
    extern __shared__ float smem[];
    const uint32_t sm_u = (uint32_t)__cvta_generic_to_shared(smem);

    const int tid  = threadIdx.x;
    const int lane = tid & 31;
    const int w    = tid >> 5;           // 0..15
    const int gid  = lane >> 2;
    const int tid4 = lane & 3;

    // GEMM warp tiling (warps 0..7): 16x32 C tiles
    const int MR = (w & 1) * 16, NC = (w >> 1) * 32;

    const ulonglong2 bias2 = ((const ulonglong2*)bias)[lane];

    // ---- prologue: W tile + first tile's staging, one group ----
    int t = blockIdx.x;
#pragma unroll
    for (int i = 0; i < 8; i++) {
        int c = tid + i * 512;                   // 4096 16B chunks
        int row = c >> 5, col = c & 31;
        cp16(sm_u + (uint32_t)(OFF_W + row * AP + col * 4) * 4u,
             g_Wt + (size_t)row * FD + col * 4);
    }
    issue_tile(t, 0, sm_u, table6, table5, table4, var_idx, idx6, nh5, nh4, tid, lane, w);
    CP_COMMIT();

    int s = 0;
    for (; t < NTILES; t += GRID, s ^= 1) {
        // issue next tile into the other stage
        int tn = t + GRID;
        if (tn < NTILES)
            issue_tile(tn, s ^ 1, sm_u, table6, table5, table4,
                       var_idx, idx6, nh5, nh4, tid, lane, w);
        CP_COMMIT();

        CP_WAIT1();            // current stage complete (newest stays in flight)
        __syncthreads();

        const int bv = t >> 10, tl = t & 1023;

        float acc[4][4];
        if (w < 8) {
            // ---- GEMM from smem ----
#pragma unroll
            for (int ni = 0; ni < 4; ni++)
#pragma unroll
                for (int r = 0; r < 4; r++) acc[ni][r] = 0.f;

            const uint32_t aB = sm_u + (uint32_t)((OFF_A + s * A_STAGE
                                 + (MR + (lane & 15)) * AP + (lane >> 4) * 4) * 4);
            const uint32_t bB = sm_u + (uint32_t)((OFF_W + (NC + lane) * AP) * 4);
#pragma unroll
            for (int k0 = 0; k0 < FD; k0 += 8) {
                uint32_t a[4], b0[4], b1[4];
                ldsm4(a, aB + k0 * 4);
                ldsm4(b0, bB + k0 * 4);
                ldsm4(b1, bB + k0 * 4 + 16);
#pragma unroll
                for (int ni = 0; ni < 4; ni++)
                    mma_tf32(acc[ni], a, b0[ni], b1[ni]);
            }
        } else {
            // ---- interpolation from staged smem rows ----
            const int iw = w - 8;                       // 0..7, points 4iw..4iw+3
            const float* sR5s = smem + OFF_R5 + s * R5_STAGE;
            const float* sR4s = smem + OFF_R4 + s * R4_STAGE;
            const float* sWts = smem + OFF_WT + s * WT_STAGE;
            const int g4 = iw >> 2;
            const float* w5p = sWts + (iw * OO5) * NHN;                      // [pt][n]
            const float* w4p = sWts + 224 + (g4 * 16 + 4 * (iw & 3)) * NHN; // [pt][n]

            u64 aL[4], aH[4];
#pragma unroll
            for (int pt = 0; pt < 4; pt++) { aL[pt] = bias2.x; aH[pt] = bias2.y; }

#pragma unroll
            for (int n = 0; n < NHN; n++) {
                ulonglong2 t4 = *(const ulonglong2*)(sR4s + (g4 * NHN + n) * FD + lane * 4);
#pragma unroll
                for (int pt = 0; pt < 4; pt++) {
                    u64 wn = pack2(w4p[pt * NHN + n]);
                    aL[pt] = fma2(wn, t4.x, aL[pt]);
                    aH[pt] = fma2(wn, t4.y, aH[pt]);
                }
            }
#pragma unroll
            for (int n = 0; n < NHN; n++) {
                ulonglong2 t5 = *(const ulonglong2*)(sR5s + (iw * NHN + n) * FD + lane * 4);
#pragma unroll
                for (int pt = 0; pt < 4; pt++) {
                    u64 wn = pack2(w5p[pt * NHN + n]);
                    aL[pt] = fma2(wn, t5.x, aL[pt]);
                    aH[pt] = fma2(wn, t5.y, aH[pt]);
                }
            }
            float* sIo = smem + OFF_IOUT;
#pragma unroll
            for (int pt = 0; pt < 4; pt++) {
                ulonglong2 o; o.x = aL[pt]; o.y = aH[pt];
                *(ulonglong2*)(sIo + (size_t)(iw * 4 + pt) * AP + lane * 4) = o;
            }
        }
        __syncthreads();

        // ---- epilogue (GEMM warps): C + interp -> gmem ----
        if (w < 8) {
            float* ob = out + ((size_t)bv * PFN + (size_t)tl * TILE_M) * ED;
            const float* sIo = smem + OFF_IOUT;
            const int row0 = MR + gid, row1 = row0 + 8;
#pragma unroll
            for (int ni = 0; ni < 4; ni++) {
                const int col = NC + ni * 8 + 2 * tid4;
                float2 i0 = *(const float2*)(sIo + (size_t)row0 * AP + col);
                float2 i1 = *(const float2*)(sIo + (size_t)row1 * AP + col);
                float2 o0, o1;
                o0.x = acc[ni][0] + i0.x;
                o0.y = acc[ni][1] + i0.y;
                o1.x = acc[ni][2] + i1.x;
                o1.y = acc[ni][3] + i1.y;
                *(float2*)(ob + (size_t)row0 * ED + col) = o0;
                *(float2*)(ob + (size_t)row1 * ED + col) = o1;
            }
        }
        __syncthreads();      // sIout reads done before next tile's interp writes
    }
}

// ---------------- launch ----------------
extern "C" void kernel_launch(void* const* d_in, const int* in_sizes, int n_in,
                              void* d_out, int out_size)
{
    const float* table6 = (const float*)d_in[0];
    const float* table5 = (const float*)d_in[1];
    const float* table4 = (const float*)d_in[2];
    const float* Wm     = (const float*)d_in[3];
    const float* bias   = (const float*)d_in[4];
    const float* rd5    = (const float*)d_in[5];
    const float* rd4    = (const float*)d_in[6];
    const float* m5     = (const float*)d_in[7];
    const float* m4     = (const float*)d_in[8];
    const int*   vidx   = (const int*)d_in[9];
    const int*   idx6   = (const int*)d_in[10];
    const int*   nh5    = (const int*)d_in[11];
    const int*   nh4    = (const int*)d_in[12];
    float* out = (float*)d_out;

    {
        int total = BB * PP5 * OO5 + BB * PP4 * OO4 + FD * ED;
        weights_kernel<<<(total + 255) / 256, 256>>>(rd5, m5, rd4, m4, Wm);
    }
    {
        cudaFuncSetAttribute(embed_kernel,
                             cudaFuncAttributeMaxDynamicSharedMemorySize, SMEM_TOTAL);
        embed_kernel<<<GRID, THREADS, SMEM_TOTAL>>>(table6, table5, table4, bias,
                                                    vidx, idx6, nh5, nh4, out);
    }
}

// round 10
// speedup vs baseline: 1.4642x; 1.4642x over previous
#include <cuda_runtime.h>
#include <cstdint>

// ---------------- problem constants ----------------
#define BB   2
#define VV   4
#define FD   128
#define ED   128
#define NHN  7
#define NN6  196608
#define NN5  49152
#define NN4  12288
#define PFN  32768
#define PP5  8192
#define PP4  2048
#define OO5  4
#define OO4  16

#define THREADS 256
#define TILE_M  64

#define AP 132                       // sA pitch (floats)
#define WP 136                       // sW pitch (floats)

#define SA_FLOATS (TILE_M * AP)      // 8448  (33.8 KB)
#define SW_FLOATS (FD * WP)          // 17408 (69.6 KB)
#define SMEM_TOTAL ((SA_FLOATS + SW_FLOATS) * 4)   // 103424 B -> 2 CTAs/SM

typedef unsigned long long u64;

// scratch (device globals allowed)
__device__ float g_w5[BB * PP5 * OO5 * NHN];
__device__ float g_w4[BB * PP4 * OO4 * NHN];
__device__ float g_Wc[FD * ED];      // W with rna tf32 rounding

// ---------------- PTX helpers (baseline sm_80+ only) ----------------
__device__ __forceinline__ uint32_t f2tf32(float f) {
    uint32_t r; asm("cvt.rna.tf32.f32 %0, %1;" : "=r"(r) : "f"(f)); return r;
}
__device__ __forceinline__ u64 pack2(float s) {
    u64 r; unsigned ui = __float_as_uint(s);
    asm("mov.b64 %0, {%1, %1};" : "=l"(r) : "r"(ui));
    return r;
}
__device__ __forceinline__ u64 fma2(u64 a, u64 b, u64 c) {
    u64 d; asm("fma.rn.f32x2 %0, %1, %2, %3;" : "=l"(d) : "l"(a), "l"(b), "l"(c)); return d;
}
__device__ __forceinline__ void mma_tf32(float* c, const uint32_t* a,
                                         uint32_t b0, uint32_t b1) {
    asm volatile(
        "mma.sync.aligned.m16n8k8.row.col.f32.tf32.tf32.f32 "
        "{%0,%1,%2,%3}, {%4,%5,%6,%7}, {%8,%9}, {%0,%1,%2,%3};"
        : "+f"(c[0]), "+f"(c[1]), "+f"(c[2]), "+f"(c[3])
        : "r"(a[0]), "r"(a[1]), "r"(a[2]), "r"(a[3]), "r"(b0), "r"(b1));
}
__device__ __forceinline__ void cp16(uint32_t dst, const void* src) {
    asm volatile("cp.async.cg.shared.global [%0], [%1], 16;" :: "r"(dst), "l"(src) : "memory");
}
#define CP_COMMIT() asm volatile("cp.async.commit_group;" ::: "memory")
#define CP_WAIT0()  asm volatile("cp.async.wait_group 0;" ::: "memory")

// ---------------- pre-pass: interp weights + W tf32(rna) copy ----------------
__global__ void weights_kernel(const float* __restrict__ rd5, const float* __restrict__ m5,
                               const float* __restrict__ rd4, const float* __restrict__ m4,
                               const float* __restrict__ Wm)
{
    const int T5 = BB * PP5 * OO5;            // 65536
    const int T4 = BB * PP4 * OO4;            // 65536
    int t = blockIdx.x * blockDim.x + threadIdx.x;
    if (t < T5) {
        int pcb = t / OO5;
        const float* rd = rd5 + (size_t)t * NHN;
        const float* mm = m5 + (size_t)pcb * NHN;
        float w[NHN]; float s = 0.f;
#pragma unroll
        for (int n = 0; n < NHN; n++) { w[n] = 1.f / (1e-20f + rd[n] + mm[n] * 1e10f); s += w[n]; }
        float inv = 1.f / s;
#pragma unroll
        for (int n = 0; n < NHN; n++) g_w5[(size_t)t * NHN + n] = w[n] * inv;
    } else if (t < T5 + T4) {
        int tt = t - T5;
        int pcb = tt / OO4;
        const float* rd = rd4 + (size_t)tt * NHN;
        const float* mm = m4 + (size_t)pcb * NHN;
        float w[NHN]; float s = 0.f;
#pragma unroll
        for (int n = 0; n < NHN; n++) { w[n] = 1.f / (1e-20f + rd[n] + mm[n] * 1e10f); s += w[n]; }
        float inv = 1.f / s;
#pragma unroll
        for (int n = 0; n < NHN; n++) g_w4[(size_t)tt * NHN + n] = w[n] * inv;
    } else if (t < T5 + T4 + FD * ED) {
        int i = t - (T5 + T4);
        ((uint32_t*)g_Wc)[i] = f2tf32(Wm[i]);
    }
}

// ---------------- fused kernel (R5 structure + variable dedup) ----------------
__global__ __launch_bounds__(THREADS, 2)
void embed_kernel(const float* __restrict__ table6, const float* __restrict__ table5,
                  const float* __restrict__ table4,
                  const float* __restrict__ bias,
                  const int* __restrict__ var_idx, const int* __restrict__ idx6,
                  const int* __restrict__ nh5, const int* __restrict__ nh4,
                  float* __restrict__ out)
{
    extern __shared__ float smem[];
    float* sA = smem;                    // [64][132]: gathered A; later interp staging
    float* sW = sA + SA_FLOATS;          // [128][136]: W row-major (tf32-rna bits)

    const int tid  = threadIdx.x;
    const int lane = tid & 31;
    const int w    = tid >> 5;           // 0..7
    const int gid  = lane >> 2;
    const int tid4 = lane & 3;

    const int bv   = blockIdx.x >> 9;    // 512 tiles per (b,v)
    const int tile = blockIdx.x & 511;
    const int b = bv >> 2, v = bv & 3;

    // ---- variable dedup: only the FIRST v with this vi computes ----
    int vrow[VV];
#pragma unroll
    for (int j = 0; j < VV; j++) vrow[j] = var_idx[b * VV + j];
    const int vi = vrow[v];
#pragma unroll
    for (int j = 0; j < VV; j++)
        if (j < v && vrow[j] == vi) return;   // uniform across block

    const float* tb6 = table6 + (size_t)vi * ((size_t)NN6 * FD);
    const float* tb5 = table5 + (size_t)vi * ((size_t)NN5 * FD);
    const float* tb4 = table4 + (size_t)vi * ((size_t)NN4 * FD);

    const uint32_t sA_u = (uint32_t)__cvta_generic_to_shared(sA);
    const uint32_t sW_u = (uint32_t)__cvta_generic_to_shared(sW);

    // ---- issue async staging: 64 gathered A rows + W tile ----
    {
        const int* i6 = idx6 + b * PFN + tile * TILE_M;
#pragma unroll
        for (int j = 0; j < 8; j++) {
            int rl = w * 8 + j;
            int row = i6[rl];
            cp16(sA_u + (uint32_t)(rl * AP * 4 + lane * 16),
                 tb6 + (size_t)row * FD + lane * 4);
        }
#pragma unroll
        for (int i = 0; i < 16; i++) {
            int c = tid + i * 256;            // 4096 16B chunks
            int row = c >> 5, col = c & 31;
            cp16(sW_u + (uint32_t)(row * WP * 4 + col * 16),
                 g_Wc + (size_t)row * FD + col * 4);
        }
        CP_COMMIT();
    }

    // ---- interpolation (overlaps copies): 8 points per warp, kept in regs ----
    u64 aL[8], aH[8];
    {
        const int pbase = tile * TILE_M + w * 8;      // multiple of 8
        const int pc5a = pbase >> 2;                  // two pc5 groups
        const int pc4  = pbase >> 4;
        const int o4   = pbase & 15;

        const int* np5 = nh5 + ((size_t)b * PP5 + pc5a) * NHN;
        const int* np4 = nh4 + ((size_t)b * PP4 + pc4) * NHN;
        const float* wp5 = g_w5 + ((size_t)(b * PP5 + pc5a)) * OO5 * NHN;
        const float* wp4 = g_w4 + (((size_t)(b * PP4 + pc4)) * OO4 + o4) * NHN;

        const ulonglong2 bias2 = ((const ulonglong2*)bias)[lane];
#pragma unroll
        for (int pt = 0; pt < 8; pt++) { aL[pt] = bias2.x; aH[pt] = bias2.y; }

        ulonglong2 t4[NHN], t5[NHN];
#pragma unroll
        for (int n = 0; n < NHN; n++)
            t4[n] = ((const ulonglong2*)(tb4 + (size_t)np4[n] * FD))[lane];
#pragma unroll
        for (int n = 0; n < NHN; n++)
            t5[n] = ((const ulonglong2*)(tb5 + (size_t)np5[n] * FD))[lane];

        // level-4: all 8 points share neighbor rows
#pragma unroll
        for (int n = 0; n < NHN; n++) {
#pragma unroll
            for (int pt = 0; pt < 8; pt++) {
                u64 wn = pack2(wp4[pt * NHN + n]);
                aL[pt] = fma2(wn, t4[n].x, aL[pt]);
                aH[pt] = fma2(wn, t4[n].y, aH[pt]);
            }
        }
        // level-5 group A: points 0..3
#pragma unroll
        for (int n = 0; n < NHN; n++) {
#pragma unroll
            for (int pt = 0; pt < 4; pt++) {
                u64 wn = pack2(wp5[pt * NHN + n]);
                aL[pt] = fma2(wn, t5[n].x, aL[pt]);
                aH[pt] = fma2(wn, t5[n].y, aH[pt]);
            }
        }
        // level-5 group B: points 4..7
#pragma unroll
        for (int n = 0; n < NHN; n++)
            t5[n] = ((const ulonglong2*)(tb5 + (size_t)np5[NHN + n] * FD))[lane];
#pragma unroll
        for (int n = 0; n < NHN; n++) {
#pragma unroll
            for (int pt = 0; pt < 4; pt++) {
                u64 wn = pack2(wp5[(OO5 + pt) * NHN + n]);
                aL[4 + pt] = fma2(wn, t5[n].x, aL[4 + pt]);
                aH[4 + pt] = fma2(wn, t5[n].y, aH[4 + pt]);
            }
        }
    }

    CP_WAIT0();
    __syncthreads();

    // ---- GEMM: warp (mw 0..1, nw 0..3) computes 32x32 of C = A @ W ----
    const int mw = w & 1, nw = w >> 1;
    const int MR = mw * 32, NC = nw * 32;
    float acc[2][4][4];
#pragma unroll
    for (int mi = 0; mi < 2; mi++)
#pragma unroll
        for (int ni = 0; ni < 4; ni++)
#pragma unroll
            for (int r = 0; r < 4; r++) acc[mi][ni][r] = 0.f;

#pragma unroll
    for (int k0 = 0; k0 < FD; k0 += 8) {
        uint32_t af[2][4];
#pragma unroll
        for (int mi = 0; mi < 2; mi++) {
            const uint32_t* ap = (const uint32_t*)sA + (MR + mi * 16 + gid) * AP + k0 + tid4;
            af[mi][0] = ap[0];
            af[mi][2] = ap[4];
            af[mi][1] = ap[8 * AP];
            af[mi][3] = ap[8 * AP + 4];
        }
#pragma unroll
        for (int ni = 0; ni < 4; ni++) {
            const uint32_t* bp = (const uint32_t*)sW + (k0 + tid4) * WP + NC + ni * 8 + gid;
            uint32_t b0 = bp[0], b1 = bp[4 * WP];
            mma_tf32(acc[0][ni], af[0], b0, b1);
            mma_tf32(acc[1][ni], af[1], b0, b1);
        }
    }
    __syncthreads();   // all A reads done; sA reusable

    // ---- stage interp regs into sA ----
#pragma unroll
    for (int pt = 0; pt < 8; pt++) {
        ulonglong2 o; o.x = aL[pt]; o.y = aH[pt];
        *(ulonglong2*)(sA + (size_t)(w * 8 + pt) * AP + lane * 4) = o;
    }
    __syncthreads();

    // ---- epilogue: C(regs) + interp(smem) -> gmem, replicated to all dup v ----
    {
#pragma unroll
        for (int v2 = 0; v2 < VV; v2++) {
            if (v2 < v || vrow[v2] != vi) continue;     // write v and its dups
            float* ob = out + (((size_t)(b * VV + v2)) * PFN + (size_t)tile * TILE_M) * ED;
#pragma unroll
            for (int mi = 0; mi < 2; mi++) {
                const int row0 = MR + mi * 16 + gid;
                const int row1 = row0 + 8;
#pragma unroll
                for (int ni = 0; ni < 4; ni++) {
                    const int col = NC + ni * 8 + 2 * tid4;
                    float2 i0 = *(const float2*)(sA + (size_t)row0 * AP + col);
                    float2 i1 = *(const float2*)(sA + (size_t)row1 * AP + col);
                    float2 o0, o1;
                    o0.x = acc[mi][ni][0] + i0.x;
                    o0.y = acc[mi][ni][1] + i0.y;
                    o1.x = acc[mi][ni][2] + i1.x;
                    o1.y = acc[mi][ni][3] + i1.y;
                    *(float2*)(ob + (size_t)row0 * ED + col) = o0;
                    *(float2*)(ob + (size_t)row1 * ED + col) = o1;
                }
            }
        }
    }
}

// ---------------- launch ----------------
extern "C" void kernel_launch(void* const* d_in, const int* in_sizes, int n_in,
                              void* d_out, int out_size)
{
    const float* table6 = (const float*)d_in[0];
    const float* table5 = (const float*)d_in[1];
    const float* table4 = (const float*)d_in[2];
    const float* Wm     = (const float*)d_in[3];
    const float* bias   = (const float*)d_in[4];
    const float* rd5    = (const float*)d_in[5];
    const float* rd4    = (const float*)d_in[6];
    const float* m5     = (const float*)d_in[7];
    const float* m4     = (const float*)d_in[8];
    const int*   vidx   = (const int*)d_in[9];
    const int*   idx6   = (const int*)d_in[10];
    const int*   nh5    = (const int*)d_in[11];
    const int*   nh4    = (const int*)d_in[12];
    float* out = (float*)d_out;

    {
        int total = BB * PP5 * OO5 + BB * PP4 * OO4 + FD * ED;
        weights_kernel<<<(total + 255) / 256, 256>>>(rd5, m5, rd4, m4, Wm);
    }
    {
        cudaFuncSetAttribute(embed_kernel,
                             cudaFuncAttributeMaxDynamicSharedMemorySize, SMEM_TOTAL);
        int grid = BB * VV * (PFN / TILE_M);   // 4096
        embed_kernel<<<grid, THREADS, SMEM_TOTAL>>>(table6, table5, table4, bias,
                                                    vidx, idx6, nh5, nh4, out);
    }
}

// round 11
// speedup vs baseline: 1.6304x; 1.1135x over previous
#include <cuda_runtime.h>
#include <cstdint>

// ---------------- problem constants ----------------
#define BB   2
#define VV   4
#define FD   128
#define ED   128
#define NHN  7
#define NN6  196608
#define NN5  49152
#define NN4  12288
#define PFN  32768
#define PP5  8192
#define PP4  2048
#define OO5  4
#define OO4  16

#define THREADS 256
#define TILE_M  64
#define GRID    304                  // 152 SMs x 2 persistent CTAs

#define AP 132                       // sA pitch (floats)
#define WP 136                       // sW pitch (floats)

// ---- smem layout (float/word offsets) ----
#define SA_O 0
#define SA_FLOATS (TILE_M * AP)          // 8448
#define SW_O SA_FLOATS
#define SW_FLOATS (FD * WP)              // 17408
#define MET_O (SW_O + SW_FLOATS)         // 25856
#define MET_W 1104                       // words per meta stage
// within a meta stage:
#define IDX6_O 0                         // 64 ints
#define NP5_O  64                        // 112 ints  [16 grp][7]
#define NP4_O  176                       // 28 ints   [4 grp][7] (+pad)
#define W5_O   208                       // 448 floats [16 grp][4 o][7]
#define W4_O   656                       // 448 floats [4 grp][16 o][7]
#define SMEM_FLOATS (MET_O + 2 * MET_W)  // 28064
#define SMEM_TOTAL (SMEM_FLOATS * 4)     // 112256 B -> 2 CTAs/SM

typedef unsigned long long u64;

// scratch (device globals allowed)
__device__ float g_w5[BB * PP5 * OO5 * NHN];
__device__ float g_w4[BB * PP4 * OO4 * NHN];
__device__ float g_Wc[FD * ED];      // W with rna tf32 rounding

// ---------------- PTX helpers (baseline sm_80+ only) ----------------
__device__ __forceinline__ uint32_t f2tf32(float f) {
    uint32_t r; asm("cvt.rna.tf32.f32 %0, %1;" : "=r"(r) : "f"(f)); return r;
}
__device__ __forceinline__ u64 pack2(float s) {
    u64 r; unsigned ui = __float_as_uint(s);
    asm("mov.b64 %0, {%1, %1};" : "=l"(r) : "r"(ui));
    return r;
}
__device__ __forceinline__ u64 fma2(u64 a, u64 b, u64 c) {
    u64 d; asm("fma.rn.f32x2 %0, %1, %2, %3;" : "=l"(d) : "l"(a), "l"(b), "l"(c)); return d;
}
__device__ __forceinline__ void mma_tf32(float* c, const uint32_t* a,
                                         uint32_t b0, uint32_t b1) {
    asm volatile(
        "mma.sync.aligned.m16n8k8.row.col.f32.tf32.tf32.f32 "
        "{%0,%1,%2,%3}, {%4,%5,%6,%7}, {%8,%9}, {%0,%1,%2,%3};"
        : "+f"(c[0]), "+f"(c[1]), "+f"(c[2]), "+f"(c[3])
        : "r"(a[0]), "r"(a[1]), "r"(a[2]), "r"(a[3]), "r"(b0), "r"(b1));
}
__device__ __forceinline__ void cp16(uint32_t dst, const void* src) {
    asm volatile("cp.async.cg.shared.global [%0], [%1], 16;" :: "r"(dst), "l"(src) : "memory");
}
#define CP_COMMIT() asm volatile("cp.async.commit_group;" ::: "memory")
#define CP_WAIT0()  asm volatile("cp.async.wait_group 0;" ::: "memory")

// ---------------- pre-pass: interp weights + W tf32(rna) copy ----------------
__global__ void weights_kernel(const float* __restrict__ rd5, const float* __restrict__ m5,
                               const float* __restrict__ rd4, const float* __restrict__ m4,
                               const float* __restrict__ Wm)
{
    const int T5 = BB * PP5 * OO5;
    const int T4 = BB * PP4 * OO4;
    int t = blockIdx.x * blockDim.x + threadIdx.x;
    if (t < T5) {
        int pcb = t / OO5;
        const float* rd = rd5 + (size_t)t * NHN;
        const float* mm = m5 + (size_t)pcb * NHN;
        float w[NHN]; float s = 0.f;
#pragma unroll
        for (int n = 0; n < NHN; n++) { w[n] = 1.f / (1e-20f + rd[n] + mm[n] * 1e10f); s += w[n]; }
        float inv = 1.f / s;
#pragma unroll
        for (int n = 0; n < NHN; n++) g_w5[(size_t)t * NHN + n] = w[n] * inv;
    } else if (t < T5 + T4) {
        int tt = t - T5;
        int pcb = tt / OO4;
        const float* rd = rd4 + (size_t)tt * NHN;
        const float* mm = m4 + (size_t)pcb * NHN;
        float w[NHN]; float s = 0.f;
#pragma unroll
        for (int n = 0; n < NHN; n++) { w[n] = 1.f / (1e-20f + rd[n] + mm[n] * 1e10f); s += w[n]; }
        float inv = 1.f / s;
#pragma unroll
        for (int n = 0; n < NHN; n++) g_w4[(size_t)tt * NHN + n] = w[n] * inv;
    } else if (t < T5 + T4 + FD * ED) {
        int i = t - (T5 + T4);
        ((uint32_t*)g_Wc)[i] = f2tf32(Wm[i]);
    }
}

// ---------------- persistent fused kernel ----------------
__global__ __launch_bounds__(THREADS, 2)
void embed_kernel(const float* __restrict__ table6, const float* __restrict__ table5,
                  const float* __restrict__ table4,
                  const float* __restrict__ bias,
                  const int* __restrict__ var_idx, const int* __restrict__ idx6,
                  const int* __restrict__ nh5, const int* __restrict__ nh4,
                  float* __restrict__ out)
{
    extern __shared__ float smem[];
    float* sA = smem + SA_O;
    float* sW = smem + SW_O;
    const uint32_t sm_u = (uint32_t)__cvta_generic_to_shared(smem);

    const int tid  = threadIdx.x;
    const int lane = tid & 31;
    const int w    = tid >> 5;           // 0..7
    const int gid  = lane >> 2;
    const int tid4 = lane & 3;

    // ---- dedup bookkeeping (uniform, packed in 2 regs) ----
    uint32_t vrpack = 0;
#pragma unroll
    for (int j = 0; j < BB * VV; j++) vrpack |= ((uint32_t)var_idx[j] & 15u) << (4 * j);
    uint32_t uniqpack = 0; int U = 0;
#pragma unroll
    for (int bv = 0; bv < BB * VV; bv++) {
        int bb = bv >> 2;
        uint32_t vi = (vrpack >> (4 * bv)) & 15u;
        bool dup = false;
#pragma unroll
        for (int j = 0; j < BB * VV; j++)
            if (j >= bb * 4 && j < bv && ((vrpack >> (4 * j)) & 15u) == vi) dup = true;
        if (!dup) { uniqpack |= (uint32_t)bv << (4 * U); U++; }
    }
    const int total = U << 9;            // 512 tiles per unique (b,vi)

    const ulonglong2 bias2 = ((const ulonglong2*)bias)[lane];

    // meta issue helper (as a macro-style lambda)
    auto issue_meta = [&](int t, int buf) {
        const int tl = t & 511;
        const int bv = (uniqpack >> (4 * (t >> 9))) & 15;
        const int b  = bv >> 2;
        const uint32_t base = sm_u + (uint32_t)(MET_O + buf * MET_W) * 4u;
        const int* i6s  = idx6 + b * PFN + tl * 64;
        const int* n5s  = nh5 + ((size_t)b * PP5 + tl * 16) * NHN;
        const int* n4s  = nh4 + ((size_t)b * PP4 + tl * 4) * NHN;
        const float* w5s = g_w5 + ((size_t)b * PP5 + tl * 16) * (OO5 * NHN);
        const float* w4s = g_w4 + ((size_t)b * PP4 + tl * 4) * (OO4 * NHN);
        for (int c = tid; c < 275; c += THREADS) {
            if (c < 16)        cp16(base + (IDX6_O + c * 4) * 4u, i6s + c * 4);
            else if (c < 44)   cp16(base + (NP5_O + (c - 16) * 4) * 4u, n5s + (c - 16) * 4);
            else if (c < 51)   cp16(base + (NP4_O + (c - 44) * 4) * 4u, n4s + (c - 44) * 4);
            else if (c < 163)  cp16(base + (W5_O + (c - 51) * 4) * 4u, w5s + (c - 51) * 4);
            else               cp16(base + (W4_O + (c - 163) * 4) * 4u, w4s + (c - 163) * 4);
        }
    };
    auto issue_A = [&](int t, int buf) {
        const int bv = (uniqpack >> (4 * (t >> 9))) & 15;
        const uint32_t vi = (vrpack >> (4 * bv)) & 15u;
        const float* tb6 = table6 + (size_t)vi * ((size_t)NN6 * FD);
        const int* i6m = (const int*)(smem + MET_O + buf * MET_W + IDX6_O);
#pragma unroll
        for (int j = 0; j < 8; j++) {
            int rl = w * 8 + j;
            int row = i6m[rl];
            cp16(sm_u + (uint32_t)(SA_O + rl * AP) * 4u + (uint32_t)lane * 16u,
                 tb6 + (size_t)row * FD + lane * 4);
        }
    };

    // ---- prologue: W + meta(t0) + meta(t0+G); wait; then A(t0) ----
    int t = blockIdx.x;
#pragma unroll
    for (int i = 0; i < 16; i++) {
        int c = tid + i * THREADS;
        int row = c >> 5, col = c & 31;
        cp16(sm_u + (uint32_t)(SW_O + row * WP) * 4u + (uint32_t)col * 16u,
             g_Wc + (size_t)row * FD + col * 4);
    }
    if (t < total) issue_meta(t, 0);
    if (t + GRID < total) issue_meta(t + GRID, 1);
    CP_COMMIT();
    CP_WAIT0();
    __syncthreads();
    if (t < total) issue_A(t, 0);
    CP_COMMIT();

    const int mw = w & 1, nw = w >> 1;
    const int MR = mw * 32, NC = nw * 32;

    int p = 0;
    for (; t < total; t += GRID, p ^= 1) {
        const int tl = t & 511;
        const int bv = (uniqpack >> (4 * (t >> 9))) & 15;
        const int b  = bv >> 2;
        const uint32_t vi = (vrpack >> (4 * bv)) & 15u;
        const float* tb5 = table5 + (size_t)vi * ((size_t)NN5 * FD);
        const float* tb4 = table4 + (size_t)vi * ((size_t)NN4 * FD);
        const float* met = smem + MET_O + p * MET_W;

        // ---- issue interp row loads (t4 + t5a) before GEMM; consume after ----
        const int* np5m = (const int*)(met + NP5_O);
        const int* np4m = (const int*)(met + NP4_O);
        ulonglong2 t4r[NHN], t5a[NHN];
        {
            const int g4 = w >> 1;
#pragma unroll
            for (int n = 0; n < NHN; n++)
                t4r[n] = ((const ulonglong2*)(tb4 + (size_t)np4m[g4 * NHN + n] * FD))[lane];
#pragma unroll
            for (int n = 0; n < NHN; n++)
                t5a[n] = ((const ulonglong2*)(tb5 + (size_t)np5m[(2 * w) * NHN + n] * FD))[lane];
        }

        CP_WAIT0();          // A(t) landed (+ meta(t+2G) from prev iter)
        __syncthreads();

        // ---- GEMM: warp (mw, nw) computes 32x32 of C = A @ W ----
        float acc[2][4][4];
#pragma unroll
        for (int mi = 0; mi < 2; mi++)
#pragma unroll
            for (int ni = 0; ni < 4; ni++)
#pragma unroll
                for (int r = 0; r < 4; r++) acc[mi][ni][r] = 0.f;

#pragma unroll
        for (int k0 = 0; k0 < FD; k0 += 8) {
            uint32_t af[2][4];
#pragma unroll
            for (int mi = 0; mi < 2; mi++) {
                const uint32_t* ap = (const uint32_t*)sA + (MR + mi * 16 + gid) * AP + k0 + tid4;
                af[mi][0] = ap[0];
                af[mi][2] = ap[4];
                af[mi][1] = ap[8 * AP];
                af[mi][3] = ap[8 * AP + 4];
            }
#pragma unroll
            for (int ni = 0; ni < 4; ni++) {
                const uint32_t* bp = (const uint32_t*)sW + (k0 + tid4) * WP + NC + ni * 8 + gid;
                uint32_t b0 = bp[0], b1 = bp[4 * WP];
                mma_tf32(acc[0][ni], af[0], b0, b1);
                mma_tf32(acc[1][ni], af[1], b0, b1);
            }
        }
        __syncthreads();     // sA reads done

        // ---- interpolation: consume t4/t5a, then t5b ----
        u64 aL[8], aH[8];
        {
            const float* w5m = met + W5_O;
            const float* w4m = met + W4_O + (w >> 1) * (OO4 * NHN) + (w & 1) * 8 * NHN;
#pragma unroll
            for (int pt = 0; pt < 8; pt++) { aL[pt] = bias2.x; aH[pt] = bias2.y; }

            // issue t5b loads now (latency hidden under fma below)
            ulonglong2 t5b[NHN];
#pragma unroll
            for (int n = 0; n < NHN; n++)
                t5b[n] = ((const ulonglong2*)(tb5 + (size_t)np5m[(2 * w + 1) * NHN + n] * FD))[lane];

            // level-4: all 8 points share rows
#pragma unroll
            for (int n = 0; n < NHN; n++) {
#pragma unroll
                for (int pt = 0; pt < 8; pt++) {
                    u64 wn = pack2(w4m[pt * NHN + n]);
                    aL[pt] = fma2(wn, t4r[n].x, aL[pt]);
                    aH[pt] = fma2(wn, t4r[n].y, aH[pt]);
                }
            }
            // level-5 group A: points 0..3
#pragma unroll
            for (int n = 0; n < NHN; n++) {
#pragma unroll
                for (int pt = 0; pt < 4; pt++) {
                    u64 wn = pack2(w5m[(w * 8 + pt) * NHN + n]);
                    aL[pt] = fma2(wn, t5a[n].x, aL[pt]);
                    aH[pt] = fma2(wn, t5a[n].y, aH[pt]);
                }
            }
            // level-5 group B: points 4..7
#pragma unroll
            for (int n = 0; n < NHN; n++) {
#pragma unroll
                for (int pt = 0; pt < 4; pt++) {
                    u64 wn = pack2(w5m[(w * 8 + 4 + pt) * NHN + n]);
                    aL[4 + pt] = fma2(wn, t5b[n].x, aL[4 + pt]);
                    aH[4 + pt] = fma2(wn, t5b[n].y, aH[4 + pt]);
                }
            }
        }

        // ---- stage interp regs into sA ----
#pragma unroll
        for (int pt = 0; pt < 8; pt++) {
            ulonglong2 o; o.x = aL[pt]; o.y = aH[pt];
            *(ulonglong2*)(sA + (size_t)(w * 8 + pt) * AP + lane * 4) = o;
        }
        __syncthreads();

        // ---- epilogue: C + interp -> gmem for bv and its dups ----
#pragma unroll
        for (int v2 = 0; v2 < VV; v2++) {
            if (((vrpack >> (4 * (b * VV + v2))) & 15u) != vi) continue;
            float* ob = out + (((size_t)(b * VV + v2)) * PFN + (size_t)tl * TILE_M) * ED;
#pragma unroll
            for (int mi = 0; mi < 2; mi++) {
                const int row0 = MR + mi * 16 + gid;
                const int row1 = row0 + 8;
#pragma unroll
                for (int ni = 0; ni < 4; ni++) {
                    const int col = NC + ni * 8 + 2 * tid4;
                    float2 i0 = *(const float2*)(sA + (size_t)row0 * AP + col);
                    float2 i1 = *(const float2*)(sA + (size_t)row1 * AP + col);
                    float2 o0, o1;
                    o0.x = acc[mi][ni][0] + i0.x;
                    o0.y = acc[mi][ni][1] + i0.y;
                    o1.x = acc[mi][ni][2] + i1.x;
                    o1.y = acc[mi][ni][3] + i1.y;
                    *(float2*)(ob + (size_t)row0 * ED + col) = o0;
                    *(float2*)(ob + (size_t)row1 * ED + col) = o1;
                }
            }
        }
        __syncthreads();     // sA reads done before next A staging

        // ---- prefetch: A(t+G) from meta buf p^1; meta(t+2G) into buf p ----
        if (t + GRID < total)     issue_A(t + GRID, p ^ 1);
        if (t + 2 * GRID < total) issue_meta(t + 2 * GRID, p);
        CP_COMMIT();
    }
}

// ---------------- launch ----------------
extern "C" void kernel_launch(void* const* d_in, const int* in_sizes, int n_in,
                              void* d_out, int out_size)
{
    const float* table6 = (const float*)d_in[0];
    const float* table5 = (const float*)d_in[1];
    const float* table4 = (const float*)d_in[2];
    const float* Wm     = (const float*)d_in[3];
    const float* bias   = (const float*)d_in[4];
    const float* rd5    = (const float*)d_in[5];
    const float* rd4    = (const float*)d_in[6];
    const float* m5     = (const float*)d_in[7];
    const float* m4     = (const float*)d_in[8];
    const int*   vidx   = (const int*)d_in[9];
    const int*   idx6   = (const int*)d_in[10];
    const int*   nh5    = (const int*)d_in[11];
    const int*   nh4    = (const int*)d_in[12];
    float* out = (float*)d_out;

    {
        int total = BB * PP5 * OO5 + BB * PP4 * OO4 + FD * ED;
        weights_kernel<<<(total + 255) / 256, 256>>>(rd5, m5, rd4, m4, Wm);
    }
    {
        cudaFuncSetAttribute(embed_kernel,
                             cudaFuncAttributeMaxDynamicSharedMemorySize, SMEM_TOTAL);
        embed_kernel<<<GRID, THREADS, SMEM_TOTAL>>>(table6, table5, table4, bias,
                                                    vidx, idx6, nh5, nh4, out);
    }
}

// round 12
// speedup vs baseline: 1.6635x; 1.0203x over previous
#include <cuda_runtime.h>
#include <cstdint>

// ---------------- problem constants ----------------
#define BB   2
#define VV   4
#define FD   128
#define ED   128
#define NHN  7
#define NN6  196608
#define NN5  49152
#define NN4  12288
#define PFN  32768
#define PP5  8192
#define PP4  2048
#define OO5  4
#define OO4  16

#define THREADS 256
#define TILE_M  64
#define GRID    304                  // 152 SMs x 2 persistent CTAs

#define AP 132                       // sA pitch (floats)
#define WP 132                       // sW pitch (floats, n-major W^T)

// ---- smem layout (float/word offsets) ----
#define SA_O 0
#define SA_FLOATS (TILE_M * AP)          // 8448
#define SW_O SA_FLOATS
#define SW_FLOATS (ED * WP)              // 16896
#define MET_O (SW_O + SW_FLOATS)         // 25344
#define MET_W 1104                       // words per meta stage
// within a meta stage:
#define IDX6_O 0                         // 64 ints
#define NP5_O  64                        // 112 ints  [16 grp][7]
#define NP4_O  176                       // 28 ints   [4 grp][7] (+pad)
#define W5_O   208                       // 448 floats [16 grp][4 o][7]
#define W4_O   656                       // 448 floats [4 grp][16 o][7]
#define SMEM_FLOATS (MET_O + 2 * MET_W)  // 27552
#define SMEM_TOTAL (SMEM_FLOATS * 4)     // 110208 B -> 2 CTAs/SM

typedef unsigned long long u64;

// scratch (device globals allowed)
__device__ float g_w5[BB * PP5 * OO5 * NHN];
__device__ float g_w4[BB * PP4 * OO4 * NHN];
__device__ float g_Wt[ED * FD];      // W transposed (n-major), rna-tf32 rounded

// ---------------- PTX helpers (baseline sm_80+ only) ----------------
__device__ __forceinline__ uint32_t f2tf32(float f) {
    uint32_t r; asm("cvt.rna.tf32.f32 %0, %1;" : "=r"(r) : "f"(f)); return r;
}
__device__ __forceinline__ u64 pack2(float s) {
    u64 r; unsigned ui = __float_as_uint(s);
    asm("mov.b64 %0, {%1, %1};" : "=l"(r) : "r"(ui));
    return r;
}
__device__ __forceinline__ u64 fma2(u64 a, u64 b, u64 c) {
    u64 d; asm("fma.rn.f32x2 %0, %1, %2, %3;" : "=l"(d) : "l"(a), "l"(b), "l"(c)); return d;
}
__device__ __forceinline__ void mma_tf32(float* c, const uint32_t* a,
                                         uint32_t b0, uint32_t b1) {
    asm volatile(
        "mma.sync.aligned.m16n8k8.row.col.f32.tf32.tf32.f32 "
        "{%0,%1,%2,%3}, {%4,%5,%6,%7}, {%8,%9}, {%0,%1,%2,%3};"
        : "+f"(c[0]), "+f"(c[1]), "+f"(c[2]), "+f"(c[3])
        : "r"(a[0]), "r"(a[1]), "r"(a[2]), "r"(a[3]), "r"(b0), "r"(b1));
}
__device__ __forceinline__ void ldsm4(uint32_t* r, uint32_t addr) {
    asm volatile("ldmatrix.sync.aligned.m8n8.x4.shared.b16 {%0,%1,%2,%3}, [%4];"
                 : "=r"(r[0]), "=r"(r[1]), "=r"(r[2]), "=r"(r[3]) : "r"(addr));
}
__device__ __forceinline__ void cp16(uint32_t dst, const void* src) {
    asm volatile("cp.async.cg.shared.global [%0], [%1], 16;" :: "r"(dst), "l"(src) : "memory");
}
#define CP_COMMIT() asm volatile("cp.async.commit_group;" ::: "memory")
#define CP_WAIT0()  asm volatile("cp.async.wait_group 0;" ::: "memory")

// ---------------- pre-pass: interp weights + W^T tf32(rna) ----------------
__global__ void weights_kernel(const float* __restrict__ rd5, const float* __restrict__ m5,
                               const float* __restrict__ rd4, const float* __restrict__ m4,
                               const float* __restrict__ Wm)
{
    const int T5 = BB * PP5 * OO5;
    const int T4 = BB * PP4 * OO4;
    int t = blockIdx.x * blockDim.x + threadIdx.x;
    if (t < T5) {
        int pcb = t / OO5;
        const float* rd = rd5 + (size_t)t * NHN;
        const float* mm = m5 + (size_t)pcb * NHN;
        float w[NHN]; float s = 0.f;
#pragma unroll
        for (int n = 0; n < NHN; n++) { w[n] = 1.f / (1e-20f + rd[n] + mm[n] * 1e10f); s += w[n]; }
        float inv = 1.f / s;
#pragma unroll
        for (int n = 0; n < NHN; n++) g_w5[(size_t)t * NHN + n] = w[n] * inv;
    } else if (t < T5 + T4) {
        int tt = t - T5;
        int pcb = tt / OO4;
        const float* rd = rd4 + (size_t)tt * NHN;
        const float* mm = m4 + (size_t)pcb * NHN;
        float w[NHN]; float s = 0.f;
#pragma unroll
        for (int n = 0; n < NHN; n++) { w[n] = 1.f / (1e-20f + rd[n] + mm[n] * 1e10f); s += w[n]; }
        float inv = 1.f / s;
#pragma unroll
        for (int n = 0; n < NHN; n++) g_w4[(size_t)tt * NHN + n] = w[n] * inv;
    } else if (t < T5 + T4 + FD * ED) {
        int i = t - (T5 + T4);
        int k = i >> 7, n = i & 127;
        ((uint32_t*)g_Wt)[n * FD + k] = f2tf32(Wm[i]);    // transpose to n-major
    }
}

// ---------------- persistent fused kernel ----------------
__global__ __launch_bounds__(THREADS, 2)
void embed_kernel(const float* __restrict__ table6, const float* __restrict__ table5,
                  const float* __restrict__ table4,
                  const float* __restrict__ bias,
                  const int* __restrict__ var_idx, const int* __restrict__ idx6,
                  const int* __restrict__ nh5, const int* __restrict__ nh4,
                  float* __restrict__ out)
{
    extern __shared__ float smem[];
    float* sA = smem + SA_O;
    const uint32_t sm_u = (uint32_t)__cvta_generic_to_shared(smem);

    const int tid  = threadIdx.x;
    const int lane = tid & 31;
    const int w    = tid >> 5;           // 0..7
    const int gid  = lane >> 2;
    const int tid4 = lane & 3;

    // ---- dedup bookkeeping (uniform, packed in 2 regs) ----
    uint32_t vrpack = 0;
#pragma unroll
    for (int j = 0; j < BB * VV; j++) vrpack |= ((uint32_t)var_idx[j] & 15u) << (4 * j);
    uint32_t uniqpack = 0; int U = 0;
#pragma unroll
    for (int bv = 0; bv < BB * VV; bv++) {
        int bb = bv >> 2;
        uint32_t vi = (vrpack >> (4 * bv)) & 15u;
        bool dup = false;
#pragma unroll
        for (int j = 0; j < BB * VV; j++)
            if (j >= bb * 4 && j < bv && ((vrpack >> (4 * j)) & 15u) == vi) dup = true;
        if (!dup) { uniqpack |= (uint32_t)bv << (4 * U); U++; }
    }
    const int total = U << 9;            // 512 tiles per unique (b,vi)

    const ulonglong2 bias2 = ((const ulonglong2*)bias)[lane];

    auto issue_meta = [&](int t, int buf) {
        const int tl = t & 511;
        const int bv = (uniqpack >> (4 * (t >> 9))) & 15;
        const int b  = bv >> 2;
        const uint32_t base = sm_u + (uint32_t)(MET_O + buf * MET_W) * 4u;
        const int* i6s  = idx6 + b * PFN + tl * 64;
        const int* n5s  = nh5 + ((size_t)b * PP5 + tl * 16) * NHN;
        const int* n4s  = nh4 + ((size_t)b * PP4 + tl * 4) * NHN;
        const float* w5s = g_w5 + ((size_t)b * PP5 + tl * 16) * (OO5 * NHN);
        const float* w4s = g_w4 + ((size_t)b * PP4 + tl * 4) * (OO4 * NHN);
        for (int c = tid; c < 275; c += THREADS) {
            if (c < 16)        cp16(base + (IDX6_O + c * 4) * 4u, i6s + c * 4);
            else if (c < 44)   cp16(base + (NP5_O + (c - 16) * 4) * 4u, n5s + (c - 16) * 4);
            else if (c < 51)   cp16(base + (NP4_O + (c - 44) * 4) * 4u, n4s + (c - 44) * 4);
            else if (c < 163)  cp16(base + (W5_O + (c - 51) * 4) * 4u, w5s + (c - 51) * 4);
            else               cp16(base + (W4_O + (c - 163) * 4) * 4u, w4s + (c - 163) * 4);
        }
    };
    auto issue_A = [&](int t, int buf) {
        const int bv = (uniqpack >> (4 * (t >> 9))) & 15;
        const uint32_t vi = (vrpack >> (4 * bv)) & 15u;
        const float* tb6 = table6 + (size_t)vi * ((size_t)NN6 * FD);
        const int* i6m = (const int*)(smem + MET_O + buf * MET_W + IDX6_O);
#pragma unroll
        for (int j = 0; j < 8; j++) {
            int rl = w * 8 + j;
            int row = i6m[rl];
            cp16(sm_u + (uint32_t)(SA_O + rl * AP) * 4u + (uint32_t)lane * 16u,
                 tb6 + (size_t)row * FD + lane * 4);
        }
    };

    // ---- prologue: W^T + meta(t0) + meta(t0+G); wait; then A(t0) ----
    int t = blockIdx.x;
#pragma unroll
    for (int i = 0; i < 16; i++) {
        int c = tid + i * THREADS;
        int row = c >> 5, col = c & 31;
        cp16(sm_u + (uint32_t)(SW_O + row * WP) * 4u + (uint32_t)col * 16u,
             g_Wt + (size_t)row * FD + col * 4);
    }
    if (t < total) issue_meta(t, 0);
    if (t + GRID < total) issue_meta(t + GRID, 1);
    CP_COMMIT();
    CP_WAIT0();
    __syncthreads();
    if (t < total) issue_A(t, 0);
    CP_COMMIT();

    const int mw = w & 1, nw = w >> 1;
    const int MR = mw * 32, NC = nw * 32;

    // ldmatrix address bases (fixed per thread)
    const uint32_t aBase = sm_u + (uint32_t)(((SA_O + (MR + (lane & 15)) * AP)
                                              + (lane >> 4) * 4) * 4);
    const uint32_t bBase = sm_u + (uint32_t)((SW_O + (NC + lane) * WP) * 4);

    int p = 0;
    for (; t < total; t += GRID, p ^= 1) {
        const int tl = t & 511;
        const int bv = (uniqpack >> (4 * (t >> 9))) & 15;
        const int b  = bv >> 2;
        const uint32_t vi = (vrpack >> (4 * bv)) & 15u;
        const float* tb5 = table5 + (size_t)vi * ((size_t)NN5 * FD);
        const float* tb4 = table4 + (size_t)vi * ((size_t)NN4 * FD);
        const float* met = smem + MET_O + p * MET_W;

        // ---- issue interp row loads (t4 + t5a) before GEMM; consume after ----
        const int* np5m = (const int*)(met + NP5_O);
        const int* np4m = (const int*)(met + NP4_O);
        ulonglong2 t4r[NHN], t5a[NHN];
        {
            const int g4 = w >> 1;
#pragma unroll
            for (int n = 0; n < NHN; n++)
                t4r[n] = ((const ulonglong2*)(tb4 + (size_t)np4m[g4 * NHN + n] * FD))[lane];
#pragma unroll
            for (int n = 0; n < NHN; n++)
                t5a[n] = ((const ulonglong2*)(tb5 + (size_t)np5m[(2 * w) * NHN + n] * FD))[lane];
        }

        CP_WAIT0();          // A(t) landed (+ meta(t+2G) from prev iter)
        __syncthreads();

        // ---- GEMM via ldmatrix + mma: 32x32 per warp ----
        float acc[2][4][4];
#pragma unroll
        for (int mi = 0; mi < 2; mi++)
#pragma unroll
            for (int ni = 0; ni < 4; ni++)
#pragma unroll
                for (int r = 0; r < 4; r++) acc[mi][ni][r] = 0.f;

#pragma unroll
        for (int k0 = 0; k0 < FD; k0 += 8) {
            uint32_t a0[4], a1[4], b0[4], b1[4];
            ldsm4(a0, aBase + k0 * 4);
            ldsm4(a1, aBase + 16 * AP * 4 + k0 * 4);
            ldsm4(b0, bBase + k0 * 4);
            ldsm4(b1, bBase + k0 * 4 + 16);
#pragma unroll
            for (int ni = 0; ni < 4; ni++) {
                mma_tf32(acc[0][ni], a0, b0[ni], b1[ni]);
                mma_tf32(acc[1][ni], a1, b0[ni], b1[ni]);
            }
        }
        __syncthreads();     // sA reads done

        // ---- interpolation: consume t4/t5a, then t5b ----
        u64 aL[8], aH[8];
        {
            const float* w5m = met + W5_O;
            const float* w4m = met + W4_O + (w >> 1) * (OO4 * NHN) + (w & 1) * 8 * NHN;
#pragma unroll
            for (int pt = 0; pt < 8; pt++) { aL[pt] = bias2.x; aH[pt] = bias2.y; }

            // issue t5b loads now (latency hidden under fma below)
            ulonglong2 t5b[NHN];
#pragma unroll
            for (int n = 0; n < NHN; n++)
                t5b[n] = ((const ulonglong2*)(tb5 + (size_t)np5m[(2 * w + 1) * NHN + n] * FD))[lane];

            // level-4: all 8 points share rows
#pragma unroll
            for (int n = 0; n < NHN; n++) {
#pragma unroll
                for (int pt = 0; pt < 8; pt++) {
                    u64 wn = pack2(w4m[pt * NHN + n]);
                    aL[pt] = fma2(wn, t4r[n].x, aL[pt]);
                    aH[pt] = fma2(wn, t4r[n].y, aH[pt]);
                }
            }
            // level-5 group A: points 0..3
#pragma unroll
            for (int n = 0; n < NHN; n++) {
#pragma unroll
                for (int pt = 0; pt < 4; pt++) {
                    u64 wn = pack2(w5m[(w * 8 + pt) * NHN + n]);
                    aL[pt] = fma2(wn, t5a[n].x, aL[pt]);
                    aH[pt] = fma2(wn, t5a[n].y, aH[pt]);
                }
            }
            // level-5 group B: points 4..7
#pragma unroll
            for (int n = 0; n < NHN; n++) {
#pragma unroll
                for (int pt = 0; pt < 4; pt++) {
                    u64 wn = pack2(w5m[(w * 8 + 4 + pt) * NHN + n]);
                    aL[4 + pt] = fma2(wn, t5b[n].x, aL[4 + pt]);
                    aH[4 + pt] = fma2(wn, t5b[n].y, aH[4 + pt]);
                }
            }
        }

        // ---- stage interp regs into sA ----
#pragma unroll
        for (int pt = 0; pt < 8; pt++) {
            ulonglong2 o; o.x = aL[pt]; o.y = aH[pt];
            *(ulonglong2*)(sA + (size_t)(w * 8 + pt) * AP + lane * 4) = o;
        }
        __syncthreads();

        // ---- epilogue: C + interp -> gmem for bv and its dups ----
#pragma unroll
        for (int v2 = 0; v2 < VV; v2++) {
            if (((vrpack >> (4 * (b * VV + v2))) & 15u) != vi) continue;
            float* ob = out + (((size_t)(b * VV + v2)) * PFN + (size_t)tl * TILE_M) * ED;
#pragma unroll
            for (int mi = 0; mi < 2; mi++) {
                const int row0 = MR + mi * 16 + gid;
                const int row1 = row0 + 8;
#pragma unroll
                for (int ni = 0; ni < 4; ni++) {
                    const int col = NC + ni * 8 + 2 * tid4;
                    float2 i0 = *(const float2*)(sA + (size_t)row0 * AP + col);
                    float2 i1 = *(const float2*)(sA + (size_t)row1 * AP + col);
                    float2 o0, o1;
                    o0.x = acc[mi][ni][0] + i0.x;
                    o0.y = acc[mi][ni][1] + i0.y;
                    o1.x = acc[mi][ni][2] + i1.x;
                    o1.y = acc[mi][ni][3] + i1.y;
                    *(float2*)(ob + (size_t)row0 * ED + col) = o0;
                    *(float2*)(ob + (size_t)row1 * ED + col) = o1;
                }
            }
        }
        __syncthreads();     // sA reads done before next A staging

        // ---- prefetch: A(t+G) from meta buf p^1; meta(t+2G) into buf p ----
        if (t + GRID < total)     issue_A(t + GRID, p ^ 1);
        if (t + 2 * GRID < total) issue_meta(t + 2 * GRID, p);
        CP_COMMIT();
    }
}

// ---------------- launch ----------------
extern "C" void kernel_launch(void* const* d_in, const int* in_sizes, int n_in,
                              void* d_out, int out_size)
{
    const float* table6 = (const float*)d_in[0];
    const float* table5 = (const float*)d_in[1];
    const float* table4 = (const float*)d_in[2];
    const float* Wm     = (const float*)d_in[3];
    const float* bias   = (const float*)d_in[4];
    const float* rd5    = (const float*)d_in[5];
    const float* rd4    = (const float*)d_in[6];
    const float* m5     = (const float*)d_in[7];
    const float* m4     = (const float*)d_in[8];
    const int*   vidx   = (const int*)d_in[9];
    const int*   idx6   = (const int*)d_in[10];
    const int*   nh5    = (const int*)d_in[11];
    const int*   nh4    = (const int*)d_in[12];
    float* out = (float*)d_out;

    {
        int total = BB * PP5 * OO5 + BB * PP4 * OO4 + FD * ED;
        weights_kernel<<<(total + 255) / 256, 256>>>(rd5, m5, rd4, m4, Wm);
    }
    {
        cudaFuncSetAttribute(embed_kernel,
                             cudaFuncAttributeMaxDynamicSharedMemorySize, SMEM_TOTAL);
        embed_kernel<<<GRID, THREADS, SMEM_TOTAL>>>(table6, table5, table4, bias,
                                                    vidx, idx6, nh5, nh4, out);
    }
}